// round 8
// baseline (speedup 1.0000x reference)
#include <cuda_runtime.h>
#include <cuda_bf16.h>
#include <math.h>

#define NMAX 50000
#define EMAX 1600000
#define SCAN_BLK 512

// ---------------- scratch (device globals; no allocations allowed) ----------
__device__ float g_h   [(size_t)NMAX * 128];
__device__ __nv_bfloat16 g_hb [(size_t)NMAX * 128];   // bf16 copy of h for gather
__device__ float g_tmp [(size_t)NMAX * 128];
__device__ float g_emb [(size_t)NMAX * 128];
__device__ float g_as  [NMAX * 2];
__device__ float g_ad  [NMAX * 2];
__device__ float g_z1  [(size_t)NMAX * 512];
__device__ float g_z2  [(size_t)NMAX * 256];
// tf32-rounded weights
__device__ float g_w1r [64 * 128];
__device__ float g_w2r [128 * 128];
__device__ float g_lw1r[128 * 512];
__device__ float g_lw2r[512 * 256];
// CSR scratch
__device__ int g_deg   [NMAX];
__device__ int g_incl  [NMAX];
__device__ int g_bsums [1024];
__device__ int g_rowptr[NMAX + 1];
__device__ int g_cursor[NMAX];
__device__ int g_csrc  [EMAX];

__device__ __forceinline__ float leaky(float v) { return v >= 0.f ? v : 0.2f * v; }

__device__ __forceinline__ unsigned f2tf32(float f) {
    unsigned r;
    asm("cvt.rna.tf32.f32 %0, %1;" : "=r"(r) : "f"(f));
    return r;
}
__device__ __forceinline__ float rnd32(float f) { return __uint_as_float(f2tf32(f)); }

__device__ __forceinline__ float4 bfu2_to_f4(uint2 u) {
    __nv_bfloat162 p0 = *reinterpret_cast<__nv_bfloat162*>(&u.x);
    __nv_bfloat162 p1 = *reinterpret_cast<__nv_bfloat162*>(&u.y);
    float2 a = __bfloat1622float2(p0);
    float2 b = __bfloat1622float2(p1);
    return make_float4(a.x, a.y, b.x, b.y);
}

// ---------------- tf32 pre-rounding for weights ------------------------------
__global__ __launch_bounds__(256) void k_round_w(
    const float* __restrict__ w1, float* __restrict__ w1r,
    const float* __restrict__ w2, float* __restrict__ w2r,
    const float* __restrict__ l1, float* __restrict__ l1r,
    const float* __restrict__ l2, float* __restrict__ l2r)
{
    const int n1 = 64 * 128, n2 = 128 * 128, n3 = 128 * 512, n4 = 512 * 256;
    int i = blockIdx.x * blockDim.x + threadIdx.x;
    if (i < n1) w1r[i] = rnd32(w1[i]);
    else if (i < n1 + n2) w2r[i - n1] = rnd32(w2[i - n1]);
    else if (i < n1 + n2 + n3) l1r[i - n1 - n2] = rnd32(l1[i - n1 - n2]);
    else if (i < n1 + n2 + n3 + n4) l2r[i - n1 - n2 - n3] = rnd32(l2[i - n1 - n2 - n3]);
}

// ================= tensor-core tf32 GEMM, cp.async double-buffered ==========
#define A_STRIDE 20
#define B_STRIDE 136

__global__ __launch_bounds__(256, 2) void k_gemm_tc(
    const float* __restrict__ A, const float* __restrict__ B,
    const float* __restrict__ bias, float* __restrict__ C,
    __nv_bfloat16* __restrict__ hb,   // optional bf16 copy of output (N must be 128)
    int M, int N, int K, int act, int rndOut, int cvtA)
{
    __shared__ float As[2][128 * A_STRIDE];
    __shared__ float Bs[2][16 * B_STRIDE];

    const int tid  = threadIdx.x;
    const int lane = tid & 31;
    const int wid  = tid >> 5;
    const int rb   = blockIdx.y * 128;
    const int cb   = blockIdx.x * 128;
    const int warpM = (wid & 3) * 32;
    const int warpN = (wid >> 2) * 64;

    const int arow = tid >> 2;
    const int acol = (tid & 3) * 4;
    const int brow = tid >> 5;
    const int bcol = (tid & 31) * 4;

    int ra0 = rb + arow;       if (ra0 >= M) ra0 = M - 1;
    int ra1 = rb + arow + 64;  if (ra1 >= M) ra1 = M - 1;
    const float* pa0 = A + (size_t)ra0 * K + acol;
    const float* pa1 = A + (size_t)ra1 * K + acol;
    const float* pb0 = B + (size_t)brow * N + cb + bcol;
    const float* pb1 = B + (size_t)(brow + 8) * N + cb + bcol;

    unsigned sa0[2], sa1[2], sb0[2], sb1[2];
    #pragma unroll
    for (int s = 0; s < 2; s++) {
        sa0[s] = (unsigned)__cvta_generic_to_shared(&As[s][arow * A_STRIDE + acol]);
        sa1[s] = (unsigned)__cvta_generic_to_shared(&As[s][(arow + 64) * A_STRIDE + acol]);
        sb0[s] = (unsigned)__cvta_generic_to_shared(&Bs[s][brow * B_STRIDE + bcol]);
        sb1[s] = (unsigned)__cvta_generic_to_shared(&Bs[s][(brow + 8) * B_STRIDE + bcol]);
    }

    float acc[2][8][4];
    #pragma unroll
    for (int i = 0; i < 2; i++)
        #pragma unroll
        for (int j = 0; j < 8; j++)
            #pragma unroll
            for (int v = 0; v < 4; v++) acc[i][j][v] = 0.f;

    const int nIt = K >> 4;

    asm volatile("cp.async.cg.shared.global [%0], [%1], 16;" :: "r"(sa0[0]), "l"(pa0));
    asm volatile("cp.async.cg.shared.global [%0], [%1], 16;" :: "r"(sa1[0]), "l"(pa1));
    asm volatile("cp.async.cg.shared.global [%0], [%1], 16;" :: "r"(sb0[0]), "l"(pb0));
    asm volatile("cp.async.cg.shared.global [%0], [%1], 16;" :: "r"(sb1[0]), "l"(pb1));
    asm volatile("cp.async.commit_group;");

    for (int it = 0; it < nIt; it++) {
        const int cur = it & 1;
        if (it + 1 < nIt) {
            const int nxt = cur ^ 1;
            int k0 = (it + 1) << 4;
            asm volatile("cp.async.cg.shared.global [%0], [%1], 16;" :: "r"(sa0[nxt]), "l"(pa0 + k0));
            asm volatile("cp.async.cg.shared.global [%0], [%1], 16;" :: "r"(sa1[nxt]), "l"(pa1 + k0));
            asm volatile("cp.async.cg.shared.global [%0], [%1], 16;" :: "r"(sb0[nxt]), "l"(pb0 + (size_t)k0 * N));
            asm volatile("cp.async.cg.shared.global [%0], [%1], 16;" :: "r"(sb1[nxt]), "l"(pb1 + (size_t)k0 * N));
            asm volatile("cp.async.commit_group;");
            asm volatile("cp.async.wait_group 1;");
        } else {
            asm volatile("cp.async.wait_group 0;");
        }
        __syncthreads();

        const float* as = As[cur];
        const float* bs = Bs[cur];
        #pragma unroll
        for (int ks = 0; ks < 2; ks++) {
            unsigned af[2][4];
            #pragma unroll
            for (int mt = 0; mt < 2; mt++) {
                int r0 = warpM + mt * 16 + (lane >> 2);
                int c0 = ks * 8 + (lane & 3);
                if (cvtA) {
                    af[mt][0] = f2tf32(as[r0 * A_STRIDE + c0]);
                    af[mt][1] = f2tf32(as[(r0 + 8) * A_STRIDE + c0]);
                    af[mt][2] = f2tf32(as[r0 * A_STRIDE + c0 + 4]);
                    af[mt][3] = f2tf32(as[(r0 + 8) * A_STRIDE + c0 + 4]);
                } else {
                    af[mt][0] = __float_as_uint(as[r0 * A_STRIDE + c0]);
                    af[mt][1] = __float_as_uint(as[(r0 + 8) * A_STRIDE + c0]);
                    af[mt][2] = __float_as_uint(as[r0 * A_STRIDE + c0 + 4]);
                    af[mt][3] = __float_as_uint(as[(r0 + 8) * A_STRIDE + c0 + 4]);
                }
            }
            unsigned bf[8][2];
            #pragma unroll
            for (int nt = 0; nt < 8; nt++) {
                int kk = ks * 8 + (lane & 3);
                int nn = warpN + nt * 8 + (lane >> 2);
                bf[nt][0] = __float_as_uint(bs[kk * B_STRIDE + nn]);
                bf[nt][1] = __float_as_uint(bs[(kk + 4) * B_STRIDE + nn]);
            }
            #pragma unroll
            for (int mt = 0; mt < 2; mt++)
                #pragma unroll
                for (int nt = 0; nt < 8; nt++) {
                    asm volatile(
                        "mma.sync.aligned.m16n8k8.row.col.f32.tf32.tf32.f32 "
                        "{%0,%1,%2,%3}, {%4,%5,%6,%7}, {%8,%9}, {%0,%1,%2,%3};"
                        : "+f"(acc[mt][nt][0]), "+f"(acc[mt][nt][1]),
                          "+f"(acc[mt][nt][2]), "+f"(acc[mt][nt][3])
                        : "r"(af[mt][0]), "r"(af[mt][1]), "r"(af[mt][2]), "r"(af[mt][3]),
                          "r"(bf[nt][0]), "r"(bf[nt][1]));
                }
        }
        __syncthreads();
    }

    #pragma unroll
    for (int mt = 0; mt < 2; mt++) {
        int r0 = rb + warpM + mt * 16 + (lane >> 2);
        #pragma unroll
        for (int nt = 0; nt < 8; nt++) {
            int c0 = cb + warpN + nt * 8 + (lane & 3) * 2;
            float b0 = 0.f, b1 = 0.f;
            if (bias) { b0 = bias[c0]; b1 = bias[c0 + 1]; }
            float v0 = acc[mt][nt][0] + b0;
            float v1 = acc[mt][nt][1] + b1;
            float v2 = acc[mt][nt][2] + b0;
            float v3 = acc[mt][nt][3] + b1;
            if (act) {
                v0 = fmaxf(v0, 0.f); v1 = fmaxf(v1, 0.f);
                v2 = fmaxf(v2, 0.f); v3 = fmaxf(v3, 0.f);
            }
            if (rndOut) {
                v0 = rnd32(v0); v1 = rnd32(v1); v2 = rnd32(v2); v3 = rnd32(v3);
            }
            if (r0 < M) {
                C[(size_t)r0 * N + c0] = v0;
                C[(size_t)r0 * N + c0 + 1] = v1;
                if (hb)
                    *reinterpret_cast<__nv_bfloat162*>(hb + (size_t)r0 * 128 + c0) =
                        __float22bfloat162_rn(make_float2(v0, v1));
            }
            if (r0 + 8 < M) {
                C[(size_t)(r0 + 8) * N + c0] = v2;
                C[(size_t)(r0 + 8) * N + c0 + 1] = v3;
                if (hb)
                    *reinterpret_cast<__nv_bfloat162*>(hb + (size_t)(r0 + 8) * 128 + c0) =
                        __float22bfloat162_rn(make_float2(v2, v3));
            }
        }
    }
}

// ================= SIMT GEMM (small-N logits only) ===========================
__global__ __launch_bounds__(256) void k_gemm(
    const float* __restrict__ A, const float* __restrict__ B,
    const float* __restrict__ bias, float* __restrict__ C,
    int M, int N, int K, int act)
{
    __shared__ float As[16][68];
    __shared__ float Bs[16][68];
    const int tid = threadIdx.x;
    const int rb = blockIdx.y * 64;
    const int cb = blockIdx.x * 64;
    const int tx = tid & 15;
    const int ty = tid >> 4;
    const int ar = tid >> 2, ak = (tid & 3) * 4;
    const int bk = tid >> 4, bc = (tid & 15) * 4;
    float acc[4][4] = {};

    for (int k0 = 0; k0 < K; k0 += 16) {
        float4 av = make_float4(0.f, 0.f, 0.f, 0.f);
        if (rb + ar < M)
            av = *(const float4*)(A + (size_t)(rb + ar) * K + k0 + ak);
        As[ak + 0][ar] = av.x; As[ak + 1][ar] = av.y;
        As[ak + 2][ar] = av.z; As[ak + 3][ar] = av.w;

        float4 bv = make_float4(0.f, 0.f, 0.f, 0.f);
        if (cb + bc < N)
            bv = *(const float4*)(B + (size_t)(k0 + bk) * N + cb + bc);
        Bs[bk][bc + 0] = bv.x; Bs[bk][bc + 1] = bv.y;
        Bs[bk][bc + 2] = bv.z; Bs[bk][bc + 3] = bv.w;
        __syncthreads();

        #pragma unroll
        for (int k = 0; k < 16; k++) {
            float4 a4 = *(const float4*)&As[k][ty * 4];
            float4 b4 = *(const float4*)&Bs[k][tx * 4];
            float a[4] = {a4.x, a4.y, a4.z, a4.w};
            float b[4] = {b4.x, b4.y, b4.z, b4.w};
            #pragma unroll
            for (int i = 0; i < 4; i++)
                #pragma unroll
                for (int j = 0; j < 4; j++)
                    acc[i][j] = fmaf(a[i], b[j], acc[i][j]);
        }
        __syncthreads();
    }

    #pragma unroll
    for (int i = 0; i < 4; i++) {
        int r = rb + ty * 4 + i;
        if (r >= M) continue;
        #pragma unroll
        for (int j = 0; j < 4; j++) {
            int c = cb + tx * 4 + j;
            if (c >= N) continue;
            float v = acc[i][j];
            if (bias) v += bias[c];
            if (act)  v = fmaxf(v, 0.f);
            C[(size_t)r * N + c] = v;
        }
    }
}

// ================= CSR construction ==========================================
__global__ __launch_bounds__(256) void k_zero(int* p, int n) {
    int i = blockIdx.x * blockDim.x + threadIdx.x;
    if (i < n) p[i] = 0;
}
// 4 edges per thread (int4), tail handled in last thread
__global__ __launch_bounds__(256) void k_hist4(
    const int* __restrict__ ei, int* deg, int nE)
{
    int i = blockIdx.x * blockDim.x + threadIdx.x;
    int base = i * 4;
    if (base + 3 < nE) {
        int4 d = *(const int4*)(ei + nE + base);
        atomicAdd(&deg[d.x], 1);
        atomicAdd(&deg[d.y], 1);
        atomicAdd(&deg[d.z], 1);
        atomicAdd(&deg[d.w], 1);
    } else {
        for (int j = base; j < nE; j++) atomicAdd(&deg[ei[nE + j]], 1);
    }
}
__global__ __launch_bounds__(SCAN_BLK) void k_scan1(
    const int* __restrict__ deg, int* incl, int* bsums, int n)
{
    __shared__ int sh[SCAN_BLK];
    int i = blockIdx.x * SCAN_BLK + threadIdx.x;
    int v = (i < n) ? deg[i] : 0;
    sh[threadIdx.x] = v;
    __syncthreads();
    for (int off = 1; off < SCAN_BLK; off <<= 1) {
        int t = (threadIdx.x >= off) ? sh[threadIdx.x - off] : 0;
        __syncthreads();
        sh[threadIdx.x] += t;
        __syncthreads();
    }
    if (i < n) incl[i] = sh[threadIdx.x];
    if (threadIdx.x == SCAN_BLK - 1) bsums[blockIdx.x] = sh[SCAN_BLK - 1];
}
__global__ __launch_bounds__(1024) void k_scan2(int* bsums, int nb) {
    __shared__ int sh[1024];
    int i = threadIdx.x;
    sh[i] = (i < nb) ? bsums[i] : 0;
    __syncthreads();
    for (int off = 1; off < 1024; off <<= 1) {
        int t = (i >= off) ? sh[i - off] : 0;
        __syncthreads();
        sh[i] += t;
        __syncthreads();
    }
    if (i < nb) bsums[i] = sh[i];
}
__global__ __launch_bounds__(SCAN_BLK) void k_scan3(
    const int* __restrict__ incl, const int* __restrict__ bsums,
    const int* __restrict__ deg, int* rowptr, int* cursor, int n)
{
    int i = blockIdx.x * SCAN_BLK + threadIdx.x;
    if (i >= n) return;
    int off = (blockIdx.x > 0) ? bsums[blockIdx.x - 1] : 0;
    int inc = incl[i] + off;
    rowptr[i + 1] = inc;
    cursor[i] = inc - deg[i];
    if (i == 0) rowptr[0] = 0;
}
__global__ __launch_bounds__(256) void k_scatter4(
    const int* __restrict__ ei, int* cursor, int* csrc, int nE)
{
    int i = blockIdx.x * blockDim.x + threadIdx.x;
    int base = i * 4;
    if (base + 3 < nE) {
        int4 s = *(const int4*)(ei + base);
        int4 d = *(const int4*)(ei + nE + base);
        int p0 = atomicAdd(&cursor[d.x], 1);
        int p1 = atomicAdd(&cursor[d.y], 1);
        int p2 = atomicAdd(&cursor[d.z], 1);
        int p3 = atomicAdd(&cursor[d.w], 1);
        csrc[p0] = s.x; csrc[p1] = s.y; csrc[p2] = s.z; csrc[p3] = s.w;
    } else {
        for (int j = base; j < nE; j++) {
            int pos = atomicAdd(&cursor[ei[nE + j]], 1);
            csrc[pos] = ei[j];
        }
    }
}

// ---------------- per-node attention dot products (warp per node) ------------
__global__ __launch_bounds__(256) void k_node_alpha(
    const float* __restrict__ h, const float* __restrict__ a_src,
    const float* __restrict__ a_dst, float* __restrict__ as_,
    float* __restrict__ ad_, int n)
{
    int w = (blockIdx.x * blockDim.x + threadIdx.x) >> 5;
    int lane = threadIdx.x & 31;
    if (w >= n) return;
    int hd = lane >> 4;

    float4 hv = ((const float4*)(h + (size_t)w * 128))[lane];
    float4 sv = ((const float4*)a_src)[lane];
    float4 dv = ((const float4*)a_dst)[lane];

    float sa = hv.x * sv.x + hv.y * sv.y + hv.z * sv.z + hv.w * sv.w;
    float sd = hv.x * dv.x + hv.y * dv.y + hv.z * dv.z + hv.w * dv.w;
    #pragma unroll
    for (int m = 8; m > 0; m >>= 1) {
        sa += __shfl_xor_sync(0xffffffffu, sa, m);
        sd += __shfl_xor_sync(0xffffffffu, sd, m);
    }
    if ((lane & 15) == 0) {
        as_[w * 2 + hd] = sa;
        ad_[w * 2 + hd] = sd;
    }
}

// ---------------- gather aggregation: warp per dst node, bf16 payload --------
__global__ __launch_bounds__(256) void k_gather(
    const int* __restrict__ rowptr, const int* __restrict__ csrc,
    const __nv_bfloat16* __restrict__ hb, const float* __restrict__ as_,
    const float* __restrict__ ad_, const float* __restrict__ bias,
    float* __restrict__ out, int n, int rndOut)
{
    int w = (blockIdx.x * blockDim.x + threadIdx.x) >> 5;
    int lane = threadIdx.x & 31;
    if (w >= n) return;
    int hd = lane >> 4;

    float add = ad_[w * 2 + hd];
    float wself = expf(leaky(as_[w * 2 + hd] + add));
    float4 hv = bfu2_to_f4(((const uint2*)(hb + (size_t)w * 128))[lane]);
    float4 acc = make_float4(hv.x * wself, hv.y * wself, hv.z * wself, hv.w * wself);
    float den = wself;

    int j = rowptr[w], end = rowptr[w + 1];
    for (; j + 3 < end; j += 4) {
        int s0 = csrc[j], s1 = csrc[j + 1], s2 = csrc[j + 2], s3 = csrc[j + 3];
        float w0 = expf(leaky(as_[s0 * 2 + hd] + add));
        float w1 = expf(leaky(as_[s1 * 2 + hd] + add));
        float w2 = expf(leaky(as_[s2 * 2 + hd] + add));
        float w3 = expf(leaky(as_[s3 * 2 + hd] + add));
        float4 h0 = bfu2_to_f4(((const uint2*)(hb + (size_t)s0 * 128))[lane]);
        float4 h1 = bfu2_to_f4(((const uint2*)(hb + (size_t)s1 * 128))[lane]);
        float4 h2 = bfu2_to_f4(((const uint2*)(hb + (size_t)s2 * 128))[lane]);
        float4 h3 = bfu2_to_f4(((const uint2*)(hb + (size_t)s3 * 128))[lane]);
        acc.x += w0 * h0.x + w1 * h1.x + w2 * h2.x + w3 * h3.x;
        acc.y += w0 * h0.y + w1 * h1.y + w2 * h2.y + w3 * h3.y;
        acc.z += w0 * h0.z + w1 * h1.z + w2 * h2.z + w3 * h3.z;
        acc.w += w0 * h0.w + w1 * h1.w + w2 * h2.w + w3 * h3.w;
        den += (w0 + w1) + (w2 + w3);
    }
    for (; j < end; j++) {
        int s0 = csrc[j];
        float w0 = expf(leaky(as_[s0 * 2 + hd] + add));
        float4 h0 = bfu2_to_f4(((const uint2*)(hb + (size_t)s0 * 128))[lane]);
        acc.x += w0 * h0.x; acc.y += w0 * h0.y;
        acc.z += w0 * h0.z; acc.w += w0 * h0.w;
        den += w0;
    }

    float inv = 1.f / (den + 1e-16f);
    float4 b = ((const float4*)bias)[lane];
    float4 o;
    o.x = fmaxf(acc.x * inv + b.x, 0.f);
    o.y = fmaxf(acc.y * inv + b.y, 0.f);
    o.z = fmaxf(acc.z * inv + b.z, 0.f);
    o.w = fmaxf(acc.w * inv + b.w, 0.f);
    if (rndOut) {
        o.x = rnd32(o.x); o.y = rnd32(o.y);
        o.z = rnd32(o.z); o.w = rnd32(o.w);
    }
    ((float4*)(out + (size_t)w * 128))[lane] = o;
}

// ---------------- launch ------------------------------------------------------
extern "C" void kernel_launch(void* const* d_in, const int* in_sizes, int n_in,
                              void* d_out, int out_size)
{
    const float* x   = (const float*)d_in[0];
    const int*   ei  = (const int*)  d_in[1];
    const float* W1  = (const float*)d_in[2];
    const float* as1 = (const float*)d_in[3];
    const float* ad1 = (const float*)d_in[4];
    const float* b1  = (const float*)d_in[5];
    const float* W2  = (const float*)d_in[6];
    const float* as2 = (const float*)d_in[7];
    const float* ad2 = (const float*)d_in[8];
    const float* b2  = (const float*)d_in[9];
    const float* lw1 = (const float*)d_in[10];
    const float* lb1 = (const float*)d_in[11];
    const float* lw2 = (const float*)d_in[12];
    const float* lb2 = (const float*)d_in[13];
    const float* lw3 = (const float*)d_in[14];
    const float* lb3 = (const float*)d_in[15];
    float* out = (float*)d_out;

    int n = in_sizes[0] / 64;
    int e = in_sizes[1] / 2;

    float *h, *tmp, *embS, *as_, *ad_, *z1, *z2;
    __nv_bfloat16 *hb;
    float *w1r, *w2r, *lw1r, *lw2r;
    int *deg, *incl, *bsums, *rowptr, *cursor, *csrc;
    cudaGetSymbolAddress((void**)&h,    g_h);
    cudaGetSymbolAddress((void**)&hb,   g_hb);
    cudaGetSymbolAddress((void**)&tmp,  g_tmp);
    cudaGetSymbolAddress((void**)&embS, g_emb);
    cudaGetSymbolAddress((void**)&as_,  g_as);
    cudaGetSymbolAddress((void**)&ad_,  g_ad);
    cudaGetSymbolAddress((void**)&z1,   g_z1);
    cudaGetSymbolAddress((void**)&z2,   g_z2);
    cudaGetSymbolAddress((void**)&w1r,  g_w1r);
    cudaGetSymbolAddress((void**)&w2r,  g_w2r);
    cudaGetSymbolAddress((void**)&lw1r, g_lw1r);
    cudaGetSymbolAddress((void**)&lw2r, g_lw2r);
    cudaGetSymbolAddress((void**)&deg,    g_deg);
    cudaGetSymbolAddress((void**)&incl,   g_incl);
    cudaGetSymbolAddress((void**)&bsums,  g_bsums);
    cudaGetSymbolAddress((void**)&rowptr, g_rowptr);
    cudaGetSymbolAddress((void**)&cursor, g_cursor);
    cudaGetSymbolAddress((void**)&csrc,   g_csrc);

    float* embPtr;
    float* logitsPtr;
    if ((long)out_size >= (long)n * 144) {
        embPtr = out;
        logitsPtr = out + (size_t)n * 128;
    } else {
        embPtr = embS;
        logitsPtr = out;
    }

    // ---- pre-round weights to tf32 ----
    const int wtot = 64*128 + 128*128 + 128*512 + 512*256;
    k_round_w<<<(wtot + 255) / 256, 256>>>(W1, w1r, W2, w2r, lw1, lw1r, lw2, lw2r);

    // ---- build CSR by destination ----
    int nscan = (n + SCAN_BLK - 1) / SCAN_BLK;
    int e4 = (e + 3) / 4;
    k_zero<<<(n + 255) / 256, 256>>>(deg, n);
    k_hist4<<<(e4 + 255) / 256, 256>>>(ei, deg, e);
    k_scan1<<<nscan, SCAN_BLK>>>(deg, incl, bsums, n);
    k_scan2<<<1, 1024>>>(bsums, nscan);
    k_scan3<<<nscan, SCAN_BLK>>>(incl, bsums, deg, rowptr, cursor, n);
    k_scatter4<<<(e4 + 255) / 256, 256>>>(ei, cursor, csrc, e);

    unsigned gy128 = (n + 127) / 128;
    int nodeGrid = (n * 32 + 255) / 256;

    // ---- GAT layer 1 ----
    k_gemm_tc<<<dim3(1, gy128), 256>>>(x, w1r, nullptr, h, hb, n, 128, 64, 0, 0, 1);
    k_node_alpha<<<nodeGrid, 256>>>(h, as1, ad1, as_, ad_, n);
    k_gather<<<nodeGrid, 256>>>(rowptr, csrc, hb, as_, ad_, b1, tmp, n, 1);

    // ---- GAT layer 2 ----
    k_gemm_tc<<<dim3(1, gy128), 256>>>(tmp, w2r, nullptr, h, hb, n, 128, 128, 0, 0, 0);
    k_node_alpha<<<nodeGrid, 256>>>(h, as2, ad2, as_, ad_, n);
    k_gather<<<nodeGrid, 256>>>(rowptr, csrc, hb, as_, ad_, b2, embPtr, n, 0);

    // ---- MLP head ----
    k_gemm_tc<<<dim3(4, gy128), 256>>>(embPtr, lw1r, lb1, z1, nullptr, n, 512, 128, 1, 1, 1);
    k_gemm_tc<<<dim3(2, gy128), 256>>>(z1, lw2r, lb2, z2, nullptr, n, 256, 512, 1, 0, 0);
    k_gemm<<<dim3(1, (n + 63) / 64), 256>>>(z2, lw3, lb3, logitsPtr, n, 16, 256, 0);
}

// round 11
// speedup vs baseline: 1.0834x; 1.0834x over previous
#include <cuda_runtime.h>
#include <math.h>

#define NMAX 50000
#define EMAX 1600000
#define SCAN_BLK 512

// ---------------- scratch (device globals; no allocations allowed) ----------
__device__ float g_h   [(size_t)NMAX * 128];
__device__ float g_tmp [(size_t)NMAX * 128];
__device__ float g_emb [(size_t)NMAX * 128];
__device__ float g_as  [NMAX * 2];
__device__ float g_ad  [NMAX * 2];
__device__ float g_z1  [(size_t)NMAX * 512];
__device__ float g_z2  [(size_t)NMAX * 256];
// tf32-rounded weights
__device__ float g_w1r [64 * 128];
__device__ float g_w2r [128 * 128];
__device__ float g_lw1r[128 * 512];
__device__ float g_lw2r[512 * 256];
// CSR scratch
__device__ int g_deg   [NMAX];
__device__ int g_incl  [NMAX];
__device__ int g_bsums [1024];
__device__ int g_rowptr[NMAX + 1];
__device__ int g_cursor[NMAX];
__device__ int g_csrc  [EMAX];

__device__ __forceinline__ float leaky(float v) { return v >= 0.f ? v : 0.2f * v; }

__device__ __forceinline__ unsigned f2tf32(float f) {
    unsigned r;
    asm("cvt.rna.tf32.f32 %0, %1;" : "=r"(r) : "f"(f));
    return r;
}
__device__ __forceinline__ float rnd32(float f) { return __uint_as_float(f2tf32(f)); }

// ---------------- tf32 pre-rounding for weights ------------------------------
__global__ __launch_bounds__(256) void k_round_w(
    const float* __restrict__ w1, float* __restrict__ w1r,
    const float* __restrict__ w2, float* __restrict__ w2r,
    const float* __restrict__ l1, float* __restrict__ l1r,
    const float* __restrict__ l2, float* __restrict__ l2r)
{
    const int n1 = 64 * 128, n2 = 128 * 128, n3 = 128 * 512, n4 = 512 * 256;
    int i = blockIdx.x * blockDim.x + threadIdx.x;
    if (i < n1) w1r[i] = rnd32(w1[i]);
    else if (i < n1 + n2) w2r[i - n1] = rnd32(w2[i - n1]);
    else if (i < n1 + n2 + n3) l1r[i - n1 - n2] = rnd32(l1[i - n1 - n2]);
    else if (i < n1 + n2 + n3 + n4) l2r[i - n1 - n2 - n3] = rnd32(l2[i - n1 - n2 - n3]);
}

// ================= tensor-core tf32 GEMM, cp.async double-buffered ==========
#define A_STRIDE 20
#define B_STRIDE 136

__global__ __launch_bounds__(256, 2) void k_gemm_tc(
    const float* __restrict__ A, const float* __restrict__ B,
    const float* __restrict__ bias, float* __restrict__ C,
    int M, int N, int K, int act, int rndOut, int cvtA)
{
    __shared__ float As[2][128 * A_STRIDE];
    __shared__ float Bs[2][16 * B_STRIDE];

    const int tid  = threadIdx.x;
    const int lane = tid & 31;
    const int wid  = tid >> 5;
    const int rb   = blockIdx.y * 128;
    const int cb   = blockIdx.x * 128;
    const int warpM = (wid & 3) * 32;
    const int warpN = (wid >> 2) * 64;

    const int arow = tid >> 2;
    const int acol = (tid & 3) * 4;
    const int brow = tid >> 5;
    const int bcol = (tid & 31) * 4;

    int ra0 = rb + arow;       if (ra0 >= M) ra0 = M - 1;
    int ra1 = rb + arow + 64;  if (ra1 >= M) ra1 = M - 1;
    const float* pa0 = A + (size_t)ra0 * K + acol;
    const float* pa1 = A + (size_t)ra1 * K + acol;
    const float* pb0 = B + (size_t)brow * N + cb + bcol;
    const float* pb1 = B + (size_t)(brow + 8) * N + cb + bcol;

    unsigned sa0[2], sa1[2], sb0[2], sb1[2];
    #pragma unroll
    for (int s = 0; s < 2; s++) {
        sa0[s] = (unsigned)__cvta_generic_to_shared(&As[s][arow * A_STRIDE + acol]);
        sa1[s] = (unsigned)__cvta_generic_to_shared(&As[s][(arow + 64) * A_STRIDE + acol]);
        sb0[s] = (unsigned)__cvta_generic_to_shared(&Bs[s][brow * B_STRIDE + bcol]);
        sb1[s] = (unsigned)__cvta_generic_to_shared(&Bs[s][(brow + 8) * B_STRIDE + bcol]);
    }

    float acc[2][8][4];
    #pragma unroll
    for (int i = 0; i < 2; i++)
        #pragma unroll
        for (int j = 0; j < 8; j++)
            #pragma unroll
            for (int v = 0; v < 4; v++) acc[i][j][v] = 0.f;

    const int nIt = K >> 4;

    asm volatile("cp.async.cg.shared.global [%0], [%1], 16;" :: "r"(sa0[0]), "l"(pa0));
    asm volatile("cp.async.cg.shared.global [%0], [%1], 16;" :: "r"(sa1[0]), "l"(pa1));
    asm volatile("cp.async.cg.shared.global [%0], [%1], 16;" :: "r"(sb0[0]), "l"(pb0));
    asm volatile("cp.async.cg.shared.global [%0], [%1], 16;" :: "r"(sb1[0]), "l"(pb1));
    asm volatile("cp.async.commit_group;");

    for (int it = 0; it < nIt; it++) {
        const int cur = it & 1;
        if (it + 1 < nIt) {
            const int nxt = cur ^ 1;
            int k0 = (it + 1) << 4;
            asm volatile("cp.async.cg.shared.global [%0], [%1], 16;" :: "r"(sa0[nxt]), "l"(pa0 + k0));
            asm volatile("cp.async.cg.shared.global [%0], [%1], 16;" :: "r"(sa1[nxt]), "l"(pa1 + k0));
            asm volatile("cp.async.cg.shared.global [%0], [%1], 16;" :: "r"(sb0[nxt]), "l"(pb0 + (size_t)k0 * N));
            asm volatile("cp.async.cg.shared.global [%0], [%1], 16;" :: "r"(sb1[nxt]), "l"(pb1 + (size_t)k0 * N));
            asm volatile("cp.async.commit_group;");
            asm volatile("cp.async.wait_group 1;");
        } else {
            asm volatile("cp.async.wait_group 0;");
        }
        __syncthreads();

        const float* as = As[cur];
        const float* bs = Bs[cur];
        #pragma unroll
        for (int ks = 0; ks < 2; ks++) {
            unsigned af[2][4];
            #pragma unroll
            for (int mt = 0; mt < 2; mt++) {
                int r0 = warpM + mt * 16 + (lane >> 2);
                int c0 = ks * 8 + (lane & 3);
                if (cvtA) {
                    af[mt][0] = f2tf32(as[r0 * A_STRIDE + c0]);
                    af[mt][1] = f2tf32(as[(r0 + 8) * A_STRIDE + c0]);
                    af[mt][2] = f2tf32(as[r0 * A_STRIDE + c0 + 4]);
                    af[mt][3] = f2tf32(as[(r0 + 8) * A_STRIDE + c0 + 4]);
                } else {
                    af[mt][0] = __float_as_uint(as[r0 * A_STRIDE + c0]);
                    af[mt][1] = __float_as_uint(as[(r0 + 8) * A_STRIDE + c0]);
                    af[mt][2] = __float_as_uint(as[r0 * A_STRIDE + c0 + 4]);
                    af[mt][3] = __float_as_uint(as[(r0 + 8) * A_STRIDE + c0 + 4]);
                }
            }
            unsigned bf[8][2];
            #pragma unroll
            for (int nt = 0; nt < 8; nt++) {
                int kk = ks * 8 + (lane & 3);
                int nn = warpN + nt * 8 + (lane >> 2);
                bf[nt][0] = __float_as_uint(bs[kk * B_STRIDE + nn]);
                bf[nt][1] = __float_as_uint(bs[(kk + 4) * B_STRIDE + nn]);
            }
            #pragma unroll
            for (int mt = 0; mt < 2; mt++)
                #pragma unroll
                for (int nt = 0; nt < 8; nt++) {
                    asm volatile(
                        "mma.sync.aligned.m16n8k8.row.col.f32.tf32.tf32.f32 "
                        "{%0,%1,%2,%3}, {%4,%5,%6,%7}, {%8,%9}, {%0,%1,%2,%3};"
                        : "+f"(acc[mt][nt][0]), "+f"(acc[mt][nt][1]),
                          "+f"(acc[mt][nt][2]), "+f"(acc[mt][nt][3])
                        : "r"(af[mt][0]), "r"(af[mt][1]), "r"(af[mt][2]), "r"(af[mt][3]),
                          "r"(bf[nt][0]), "r"(bf[nt][1]));
                }
        }
        __syncthreads();
    }

    #pragma unroll
    for (int mt = 0; mt < 2; mt++) {
        int r0 = rb + warpM + mt * 16 + (lane >> 2);
        #pragma unroll
        for (int nt = 0; nt < 8; nt++) {
            int c0 = cb + warpN + nt * 8 + (lane & 3) * 2;
            float b0 = 0.f, b1 = 0.f;
            if (bias) { b0 = bias[c0]; b1 = bias[c0 + 1]; }
            float v0 = acc[mt][nt][0] + b0;
            float v1 = acc[mt][nt][1] + b1;
            float v2 = acc[mt][nt][2] + b0;
            float v3 = acc[mt][nt][3] + b1;
            if (act) {
                v0 = fmaxf(v0, 0.f); v1 = fmaxf(v1, 0.f);
                v2 = fmaxf(v2, 0.f); v3 = fmaxf(v3, 0.f);
            }
            if (rndOut) {
                v0 = rnd32(v0); v1 = rnd32(v1); v2 = rnd32(v2); v3 = rnd32(v3);
            }
            if (r0 < M) {
                C[(size_t)r0 * N + c0] = v0;
                C[(size_t)r0 * N + c0 + 1] = v1;
            }
            if (r0 + 8 < M) {
                C[(size_t)(r0 + 8) * N + c0] = v2;
                C[(size_t)(r0 + 8) * N + c0 + 1] = v3;
            }
        }
    }
}

// ================= SIMT GEMM (small-N logits only) ===========================
__global__ __launch_bounds__(256) void k_gemm(
    const float* __restrict__ A, const float* __restrict__ B,
    const float* __restrict__ bias, float* __restrict__ C,
    int M, int N, int K, int act)
{
    __shared__ float As[16][68];
    __shared__ float Bs[16][68];
    const int tid = threadIdx.x;
    const int rb = blockIdx.y * 64;
    const int cb = blockIdx.x * 64;
    const int tx = tid & 15;
    const int ty = tid >> 4;
    const int ar = tid >> 2, ak = (tid & 3) * 4;
    const int bk = tid >> 4, bc = (tid & 15) * 4;
    float acc[4][4] = {};

    for (int k0 = 0; k0 < K; k0 += 16) {
        float4 av = make_float4(0.f, 0.f, 0.f, 0.f);
        if (rb + ar < M)
            av = *(const float4*)(A + (size_t)(rb + ar) * K + k0 + ak);
        As[ak + 0][ar] = av.x; As[ak + 1][ar] = av.y;
        As[ak + 2][ar] = av.z; As[ak + 3][ar] = av.w;

        float4 bv = make_float4(0.f, 0.f, 0.f, 0.f);
        if (cb + bc < N)
            bv = *(const float4*)(B + (size_t)(k0 + bk) * N + cb + bc);
        Bs[bk][bc + 0] = bv.x; Bs[bk][bc + 1] = bv.y;
        Bs[bk][bc + 2] = bv.z; Bs[bk][bc + 3] = bv.w;
        __syncthreads();

        #pragma unroll
        for (int k = 0; k < 16; k++) {
            float4 a4 = *(const float4*)&As[k][ty * 4];
            float4 b4 = *(const float4*)&Bs[k][tx * 4];
            float a[4] = {a4.x, a4.y, a4.z, a4.w};
            float b[4] = {b4.x, b4.y, b4.z, b4.w};
            #pragma unroll
            for (int i = 0; i < 4; i++)
                #pragma unroll
                for (int j = 0; j < 4; j++)
                    acc[i][j] = fmaf(a[i], b[j], acc[i][j]);
        }
        __syncthreads();
    }

    #pragma unroll
    for (int i = 0; i < 4; i++) {
        int r = rb + ty * 4 + i;
        if (r >= M) continue;
        #pragma unroll
        for (int j = 0; j < 4; j++) {
            int c = cb + tx * 4 + j;
            if (c >= N) continue;
            float v = acc[i][j];
            if (bias) v += bias[c];
            if (act)  v = fmaxf(v, 0.f);
            C[(size_t)r * N + c] = v;
        }
    }
}

// ================= CSR construction ==========================================
__global__ __launch_bounds__(256) void k_zero(int* p, int n) {
    int i = blockIdx.x * blockDim.x + threadIdx.x;
    if (i < n) p[i] = 0;
}
__global__ __launch_bounds__(256) void k_hist4(
    const int* __restrict__ ei, int* deg, int nE)
{
    int i = blockIdx.x * blockDim.x + threadIdx.x;
    int base = i * 4;
    if (base + 3 < nE) {
        int4 d = *(const int4*)(ei + nE + base);
        atomicAdd(&deg[d.x], 1);
        atomicAdd(&deg[d.y], 1);
        atomicAdd(&deg[d.z], 1);
        atomicAdd(&deg[d.w], 1);
    } else {
        for (int j = base; j < nE; j++) atomicAdd(&deg[ei[nE + j]], 1);
    }
}
__global__ __launch_bounds__(SCAN_BLK) void k_scan1(
    const int* __restrict__ deg, int* incl, int* bsums, int n)
{
    __shared__ int sh[SCAN_BLK];
    int i = blockIdx.x * SCAN_BLK + threadIdx.x;
    int v = (i < n) ? deg[i] : 0;
    sh[threadIdx.x] = v;
    __syncthreads();
    for (int off = 1; off < SCAN_BLK; off <<= 1) {
        int t = (threadIdx.x >= off) ? sh[threadIdx.x - off] : 0;
        __syncthreads();
        sh[threadIdx.x] += t;
        __syncthreads();
    }
    if (i < n) incl[i] = sh[threadIdx.x];
    if (threadIdx.x == SCAN_BLK - 1) bsums[blockIdx.x] = sh[SCAN_BLK - 1];
}
__global__ __launch_bounds__(1024) void k_scan2(int* bsums, int nb) {
    __shared__ int sh[1024];
    int i = threadIdx.x;
    sh[i] = (i < nb) ? bsums[i] : 0;
    __syncthreads();
    for (int off = 1; off < 1024; off <<= 1) {
        int t = (i >= off) ? sh[i - off] : 0;
        __syncthreads();
        sh[i] += t;
        __syncthreads();
    }
    if (i < nb) bsums[i] = sh[i];
}
__global__ __launch_bounds__(SCAN_BLK) void k_scan3(
    const int* __restrict__ incl, const int* __restrict__ bsums,
    const int* __restrict__ deg, int* rowptr, int* cursor, int n)
{
    int i = blockIdx.x * SCAN_BLK + threadIdx.x;
    if (i >= n) return;
    int off = (blockIdx.x > 0) ? bsums[blockIdx.x - 1] : 0;
    int inc = incl[i] + off;
    rowptr[i + 1] = inc;
    cursor[i] = inc - deg[i];
    if (i == 0) rowptr[0] = 0;
}
__global__ __launch_bounds__(256) void k_scatter4(
    const int* __restrict__ ei, int* cursor, int* csrc, int nE)
{
    int i = blockIdx.x * blockDim.x + threadIdx.x;
    int base = i * 4;
    if (base + 3 < nE) {
        int4 s = *(const int4*)(ei + base);
        int4 d = *(const int4*)(ei + nE + base);
        int p0 = atomicAdd(&cursor[d.x], 1);
        int p1 = atomicAdd(&cursor[d.y], 1);
        int p2 = atomicAdd(&cursor[d.z], 1);
        int p3 = atomicAdd(&cursor[d.w], 1);
        csrc[p0] = s.x; csrc[p1] = s.y; csrc[p2] = s.z; csrc[p3] = s.w;
    } else {
        for (int j = base; j < nE; j++) {
            int pos = atomicAdd(&cursor[ei[nE + j]], 1);
            csrc[pos] = ei[j];
        }
    }
}

// ---------------- per-node attention dot products (warp per node) ------------
__global__ __launch_bounds__(256) void k_node_alpha(
    const float* __restrict__ h, const float* __restrict__ a_src,
    const float* __restrict__ a_dst, float* __restrict__ as_,
    float* __restrict__ ad_, int n)
{
    int w = (blockIdx.x * blockDim.x + threadIdx.x) >> 5;
    int lane = threadIdx.x & 31;
    if (w >= n) return;
    int hd = lane >> 4;

    float4 hv = ((const float4*)(h + (size_t)w * 128))[lane];
    float4 sv = ((const float4*)a_src)[lane];
    float4 dv = ((const float4*)a_dst)[lane];

    float sa = hv.x * sv.x + hv.y * sv.y + hv.z * sv.z + hv.w * sv.w;
    float sd = hv.x * dv.x + hv.y * dv.y + hv.z * dv.z + hv.w * dv.w;
    #pragma unroll
    for (int m = 8; m > 0; m >>= 1) {
        sa += __shfl_xor_sync(0xffffffffu, sa, m);
        sd += __shfl_xor_sync(0xffffffffu, sd, m);
    }
    if ((lane & 15) == 0) {
        as_[w * 2 + hd] = sa;
        ad_[w * 2 + hd] = sd;
    }
}

// ---------------- gather aggregation: warp per dst node (fp32, 8-wide) -------
__global__ __launch_bounds__(256) void k_gather(
    const int* __restrict__ rowptr, const int* __restrict__ csrc,
    const float* __restrict__ h, const float* __restrict__ as_,
    const float* __restrict__ ad_, const float* __restrict__ bias,
    float* __restrict__ out, int n, int rndOut)
{
    int w = (blockIdx.x * blockDim.x + threadIdx.x) >> 5;
    int lane = threadIdx.x & 31;
    if (w >= n) return;
    int hd = lane >> 4;

    float add = ad_[w * 2 + hd];
    float wself = expf(leaky(as_[w * 2 + hd] + add));
    float4 hv = ((const float4*)(h + (size_t)w * 128))[lane];
    float4 acc = make_float4(hv.x * wself, hv.y * wself, hv.z * wself, hv.w * wself);
    float den = wself;

    int j = rowptr[w], end = rowptr[w + 1];
    // 8-wide unroll: 8 independent load chains in flight
    for (; j + 7 < end; j += 8) {
        int s[8];
        #pragma unroll
        for (int q = 0; q < 8; q++) s[q] = csrc[j + q];
        float wq[8];
        #pragma unroll
        for (int q = 0; q < 8; q++) wq[q] = expf(leaky(as_[s[q] * 2 + hd] + add));
        float4 hq[8];
        #pragma unroll
        for (int q = 0; q < 8; q++)
            hq[q] = ((const float4*)(h + (size_t)s[q] * 128))[lane];
        #pragma unroll
        for (int q = 0; q < 8; q++) {
            acc.x += wq[q] * hq[q].x;
            acc.y += wq[q] * hq[q].y;
            acc.z += wq[q] * hq[q].z;
            acc.w += wq[q] * hq[q].w;
            den += wq[q];
        }
    }
    for (; j + 1 < end; j += 2) {
        int s0 = csrc[j], s1 = csrc[j + 1];
        float w0 = expf(leaky(as_[s0 * 2 + hd] + add));
        float w1 = expf(leaky(as_[s1 * 2 + hd] + add));
        float4 h0 = ((const float4*)(h + (size_t)s0 * 128))[lane];
        float4 h1 = ((const float4*)(h + (size_t)s1 * 128))[lane];
        acc.x += w0 * h0.x + w1 * h1.x;
        acc.y += w0 * h0.y + w1 * h1.y;
        acc.z += w0 * h0.z + w1 * h1.z;
        acc.w += w0 * h0.w + w1 * h1.w;
        den += w0 + w1;
    }
    if (j < end) {
        int s0 = csrc[j];
        float w0 = expf(leaky(as_[s0 * 2 + hd] + add));
        float4 h0 = ((const float4*)(h + (size_t)s0 * 128))[lane];
        acc.x += w0 * h0.x; acc.y += w0 * h0.y;
        acc.z += w0 * h0.z; acc.w += w0 * h0.w;
        den += w0;
    }

    float inv = 1.f / (den + 1e-16f);
    float4 b = ((const float4*)bias)[lane];
    float4 o;
    o.x = fmaxf(acc.x * inv + b.x, 0.f);
    o.y = fmaxf(acc.y * inv + b.y, 0.f);
    o.z = fmaxf(acc.z * inv + b.z, 0.f);
    o.w = fmaxf(acc.w * inv + b.w, 0.f);
    if (rndOut) {
        o.x = rnd32(o.x); o.y = rnd32(o.y);
        o.z = rnd32(o.z); o.w = rnd32(o.w);
    }
    ((float4*)(out + (size_t)w * 128))[lane] = o;
}

// ---------------- launch ------------------------------------------------------
extern "C" void kernel_launch(void* const* d_in, const int* in_sizes, int n_in,
                              void* d_out, int out_size)
{
    const float* x   = (const float*)d_in[0];
    const int*   ei  = (const int*)  d_in[1];
    const float* W1  = (const float*)d_in[2];
    const float* as1 = (const float*)d_in[3];
    const float* ad1 = (const float*)d_in[4];
    const float* b1  = (const float*)d_in[5];
    const float* W2  = (const float*)d_in[6];
    const float* as2 = (const float*)d_in[7];
    const float* ad2 = (const float*)d_in[8];
    const float* b2  = (const float*)d_in[9];
    const float* lw1 = (const float*)d_in[10];
    const float* lb1 = (const float*)d_in[11];
    const float* lw2 = (const float*)d_in[12];
    const float* lb2 = (const float*)d_in[13];
    const float* lw3 = (const float*)d_in[14];
    const float* lb3 = (const float*)d_in[15];
    float* out = (float*)d_out;

    int n = in_sizes[0] / 64;
    int e = in_sizes[1] / 2;

    float *h, *tmp, *embS, *as_, *ad_, *z1, *z2;
    float *w1r, *w2r, *lw1r, *lw2r;
    int *deg, *incl, *bsums, *rowptr, *cursor, *csrc;
    cudaGetSymbolAddress((void**)&h,    g_h);
    cudaGetSymbolAddress((void**)&tmp,  g_tmp);
    cudaGetSymbolAddress((void**)&embS, g_emb);
    cudaGetSymbolAddress((void**)&as_,  g_as);
    cudaGetSymbolAddress((void**)&ad_,  g_ad);
    cudaGetSymbolAddress((void**)&z1,   g_z1);
    cudaGetSymbolAddress((void**)&z2,   g_z2);
    cudaGetSymbolAddress((void**)&w1r,  g_w1r);
    cudaGetSymbolAddress((void**)&w2r,  g_w2r);
    cudaGetSymbolAddress((void**)&lw1r, g_lw1r);
    cudaGetSymbolAddress((void**)&lw2r, g_lw2r);
    cudaGetSymbolAddress((void**)&deg,    g_deg);
    cudaGetSymbolAddress((void**)&incl,   g_incl);
    cudaGetSymbolAddress((void**)&bsums,  g_bsums);
    cudaGetSymbolAddress((void**)&rowptr, g_rowptr);
    cudaGetSymbolAddress((void**)&cursor, g_cursor);
    cudaGetSymbolAddress((void**)&csrc,   g_csrc);

    float* embPtr;
    float* logitsPtr;
    if ((long)out_size >= (long)n * 144) {
        embPtr = out;
        logitsPtr = out + (size_t)n * 128;
    } else {
        embPtr = embS;
        logitsPtr = out;
    }

    // ---- pre-round weights to tf32 ----
    const int wtot = 64*128 + 128*128 + 128*512 + 512*256;
    k_round_w<<<(wtot + 255) / 256, 256>>>(W1, w1r, W2, w2r, lw1, lw1r, lw2, lw2r);

    // ---- build CSR by destination ----
    int nscan = (n + SCAN_BLK - 1) / SCAN_BLK;
    int e4 = (e + 3) / 4;
    k_zero<<<(n + 255) / 256, 256>>>(deg, n);
    k_hist4<<<(e4 + 255) / 256, 256>>>(ei, deg, e);
    k_scan1<<<nscan, SCAN_BLK>>>(deg, incl, bsums, n);
    k_scan2<<<1, 1024>>>(bsums, nscan);
    k_scan3<<<nscan, SCAN_BLK>>>(incl, bsums, deg, rowptr, cursor, n);
    k_scatter4<<<(e4 + 255) / 256, 256>>>(ei, cursor, csrc, e);

    unsigned gy128 = (n + 127) / 128;
    int nodeGrid = (n * 32 + 255) / 256;

    // ---- GAT layer 1 ----
    k_gemm_tc<<<dim3(1, gy128), 256>>>(x, w1r, nullptr, h, n, 128, 64, 0, 0, 1);
    k_node_alpha<<<nodeGrid, 256>>>(h, as1, ad1, as_, ad_, n);
    k_gather<<<nodeGrid, 256>>>(rowptr, csrc, h, as_, ad_, b1, tmp, n, 1);

    // ---- GAT layer 2 ----
    k_gemm_tc<<<dim3(1, gy128), 256>>>(tmp, w2r, nullptr, h, n, 128, 128, 0, 0, 0);
    k_node_alpha<<<nodeGrid, 256>>>(h, as2, ad2, as_, ad_, n);
    k_gather<<<nodeGrid, 256>>>(rowptr, csrc, h, as_, ad_, b2, embPtr, n, 0);

    // ---- MLP head ----
    k_gemm_tc<<<dim3(4, gy128), 256>>>(embPtr, lw1r, lb1, z1, n, 512, 128, 1, 1, 1);
    k_gemm_tc<<<dim3(2, gy128), 256>>>(z1, lw2r, lb2, z2, n, 256, 512, 1, 0, 0);
    k_gemm<<<dim3(1, (n + 63) / 64), 256>>>(z2, lw3, lb3, logitsPtr, n, 16, 256, 0);
}

// round 14
// speedup vs baseline: 1.1640x; 1.0744x over previous
#include <cuda_runtime.h>
#include <math.h>

#define NMAX 50000
#define EMAX 1600000
#define SCAN_BLK 512

// ---------------- scratch (device globals; no allocations allowed) ----------
__device__ float g_h   [(size_t)NMAX * 128];
__device__ float g_tmp [(size_t)NMAX * 128];
__device__ float g_emb [(size_t)NMAX * 128];
__device__ float g_as  [NMAX * 2];
__device__ float g_ad  [NMAX * 2];
__device__ float g_z1  [(size_t)NMAX * 512];
__device__ float g_z2  [(size_t)NMAX * 256];
// tf32-rounded weights
__device__ float g_w1r [64 * 128];
__device__ float g_w2r [128 * 128];
__device__ float g_lw1r[128 * 512];
__device__ float g_lw2r[512 * 256];
// CSR scratch
__device__ int g_deg   [NMAX];
__device__ int g_incl  [NMAX];
__device__ int g_bsums [1024];
__device__ int g_rowptr[NMAX + 1];
__device__ int g_cursor[NMAX];
__device__ int g_csrc  [EMAX];

__device__ __forceinline__ float leaky(float v) { return v >= 0.f ? v : 0.2f * v; }

__device__ __forceinline__ unsigned f2tf32(float f) {
    unsigned r;
    asm("cvt.rna.tf32.f32 %0, %1;" : "=r"(r) : "f"(f));
    return r;
}
__device__ __forceinline__ float rnd32(float f) { return __uint_as_float(f2tf32(f)); }

// ---------------- tf32 pre-rounding for weights ------------------------------
__global__ __launch_bounds__(256) void k_round_w(
    const float* __restrict__ w1, float* __restrict__ w1r,
    const float* __restrict__ w2, float* __restrict__ w2r,
    const float* __restrict__ l1, float* __restrict__ l1r,
    const float* __restrict__ l2, float* __restrict__ l2r)
{
    const int n1 = 64 * 128, n2 = 128 * 128, n3 = 128 * 512, n4 = 512 * 256;
    int i = blockIdx.x * blockDim.x + threadIdx.x;
    if (i < n1) w1r[i] = rnd32(w1[i]);
    else if (i < n1 + n2) w2r[i - n1] = rnd32(w2[i - n1]);
    else if (i < n1 + n2 + n3) l1r[i - n1 - n2] = rnd32(l1[i - n1 - n2]);
    else if (i < n1 + n2 + n3 + n4) l2r[i - n1 - n2 - n3] = rnd32(l2[i - n1 - n2 - n3]);
}

// ================= tensor-core tf32 GEMM, cp.async double-buffered ==========
// Optional fused attention-alpha epilogue (aSrc != null): requires N==128,
// gridDim.x==1; each warp's 64-col span == one head.
#define A_STRIDE 20
#define B_STRIDE 136

__global__ __launch_bounds__(256, 2) void k_gemm_tc(
    const float* __restrict__ A, const float* __restrict__ B,
    const float* __restrict__ bias, float* __restrict__ C,
    int M, int N, int K, int act, int rndOut, int cvtA,
    const float* __restrict__ aSrc, const float* __restrict__ aDst,
    float* __restrict__ asOut, float* __restrict__ adOut)
{
    __shared__ float As[2][128 * A_STRIDE];
    __shared__ float Bs[2][16 * B_STRIDE];

    const int tid  = threadIdx.x;
    const int lane = tid & 31;
    const int wid  = tid >> 5;
    const int rb   = blockIdx.y * 128;
    const int cb   = blockIdx.x * 128;
    const int warpM = (wid & 3) * 32;
    const int warpN = (wid >> 2) * 64;

    const int arow = tid >> 2;
    const int acol = (tid & 3) * 4;
    const int brow = tid >> 5;
    const int bcol = (tid & 31) * 4;

    int ra0 = rb + arow;       if (ra0 >= M) ra0 = M - 1;
    int ra1 = rb + arow + 64;  if (ra1 >= M) ra1 = M - 1;
    const float* pa0 = A + (size_t)ra0 * K + acol;
    const float* pa1 = A + (size_t)ra1 * K + acol;
    const float* pb0 = B + (size_t)brow * N + cb + bcol;
    const float* pb1 = B + (size_t)(brow + 8) * N + cb + bcol;

    unsigned sa0[2], sa1[2], sb0[2], sb1[2];
    #pragma unroll
    for (int s = 0; s < 2; s++) {
        sa0[s] = (unsigned)__cvta_generic_to_shared(&As[s][arow * A_STRIDE + acol]);
        sa1[s] = (unsigned)__cvta_generic_to_shared(&As[s][(arow + 64) * A_STRIDE + acol]);
        sb0[s] = (unsigned)__cvta_generic_to_shared(&Bs[s][brow * B_STRIDE + bcol]);
        sb1[s] = (unsigned)__cvta_generic_to_shared(&Bs[s][(brow + 8) * B_STRIDE + bcol]);
    }

    float acc[2][8][4];
    #pragma unroll
    for (int i = 0; i < 2; i++)
        #pragma unroll
        for (int j = 0; j < 8; j++)
            #pragma unroll
            for (int v = 0; v < 4; v++) acc[i][j][v] = 0.f;

    const int nIt = K >> 4;

    asm volatile("cp.async.cg.shared.global [%0], [%1], 16;" :: "r"(sa0[0]), "l"(pa0));
    asm volatile("cp.async.cg.shared.global [%0], [%1], 16;" :: "r"(sa1[0]), "l"(pa1));
    asm volatile("cp.async.cg.shared.global [%0], [%1], 16;" :: "r"(sb0[0]), "l"(pb0));
    asm volatile("cp.async.cg.shared.global [%0], [%1], 16;" :: "r"(sb1[0]), "l"(pb1));
    asm volatile("cp.async.commit_group;");

    for (int it = 0; it < nIt; it++) {
        const int cur = it & 1;
        if (it + 1 < nIt) {
            const int nxt = cur ^ 1;
            int k0 = (it + 1) << 4;
            asm volatile("cp.async.cg.shared.global [%0], [%1], 16;" :: "r"(sa0[nxt]), "l"(pa0 + k0));
            asm volatile("cp.async.cg.shared.global [%0], [%1], 16;" :: "r"(sa1[nxt]), "l"(pa1 + k0));
            asm volatile("cp.async.cg.shared.global [%0], [%1], 16;" :: "r"(sb0[nxt]), "l"(pb0 + (size_t)k0 * N));
            asm volatile("cp.async.cg.shared.global [%0], [%1], 16;" :: "r"(sb1[nxt]), "l"(pb1 + (size_t)k0 * N));
            asm volatile("cp.async.commit_group;");
            asm volatile("cp.async.wait_group 1;");
        } else {
            asm volatile("cp.async.wait_group 0;");
        }
        __syncthreads();

        const float* as = As[cur];
        const float* bs = Bs[cur];
        #pragma unroll
        for (int ks = 0; ks < 2; ks++) {
            unsigned af[2][4];
            #pragma unroll
            for (int mt = 0; mt < 2; mt++) {
                int r0 = warpM + mt * 16 + (lane >> 2);
                int c0 = ks * 8 + (lane & 3);
                if (cvtA) {
                    af[mt][0] = f2tf32(as[r0 * A_STRIDE + c0]);
                    af[mt][1] = f2tf32(as[(r0 + 8) * A_STRIDE + c0]);
                    af[mt][2] = f2tf32(as[r0 * A_STRIDE + c0 + 4]);
                    af[mt][3] = f2tf32(as[(r0 + 8) * A_STRIDE + c0 + 4]);
                } else {
                    af[mt][0] = __float_as_uint(as[r0 * A_STRIDE + c0]);
                    af[mt][1] = __float_as_uint(as[(r0 + 8) * A_STRIDE + c0]);
                    af[mt][2] = __float_as_uint(as[r0 * A_STRIDE + c0 + 4]);
                    af[mt][3] = __float_as_uint(as[(r0 + 8) * A_STRIDE + c0 + 4]);
                }
            }
            unsigned bf[8][2];
            #pragma unroll
            for (int nt = 0; nt < 8; nt++) {
                int kk = ks * 8 + (lane & 3);
                int nn = warpN + nt * 8 + (lane >> 2);
                bf[nt][0] = __float_as_uint(bs[kk * B_STRIDE + nn]);
                bf[nt][1] = __float_as_uint(bs[(kk + 4) * B_STRIDE + nn]);
            }
            #pragma unroll
            for (int mt = 0; mt < 2; mt++)
                #pragma unroll
                for (int nt = 0; nt < 8; nt++) {
                    asm volatile(
                        "mma.sync.aligned.m16n8k8.row.col.f32.tf32.tf32.f32 "
                        "{%0,%1,%2,%3}, {%4,%5,%6,%7}, {%8,%9}, {%0,%1,%2,%3};"
                        : "+f"(acc[mt][nt][0]), "+f"(acc[mt][nt][1]),
                          "+f"(acc[mt][nt][2]), "+f"(acc[mt][nt][3])
                        : "r"(af[mt][0]), "r"(af[mt][1]), "r"(af[mt][2]), "r"(af[mt][3]),
                          "r"(bf[nt][0]), "r"(bf[nt][1]));
                }
        }
        __syncthreads();
    }

    // ---- epilogue: bias / relu / tf32-round, optional alpha fusion ----
    float saR[2][2] = {{0.f, 0.f}, {0.f, 0.f}};
    float sdR[2][2] = {{0.f, 0.f}, {0.f, 0.f}};

    #pragma unroll
    for (int mt = 0; mt < 2; mt++) {
        int r0 = rb + warpM + mt * 16 + (lane >> 2);
        #pragma unroll
        for (int nt = 0; nt < 8; nt++) {
            int c0 = cb + warpN + nt * 8 + (lane & 3) * 2;
            float b0 = 0.f, b1 = 0.f;
            if (bias) { b0 = bias[c0]; b1 = bias[c0 + 1]; }
            float v0 = acc[mt][nt][0] + b0;
            float v1 = acc[mt][nt][1] + b1;
            float v2 = acc[mt][nt][2] + b0;
            float v3 = acc[mt][nt][3] + b1;
            if (act) {
                v0 = fmaxf(v0, 0.f); v1 = fmaxf(v1, 0.f);
                v2 = fmaxf(v2, 0.f); v3 = fmaxf(v3, 0.f);
            }
            if (rndOut) {
                v0 = rnd32(v0); v1 = rnd32(v1); v2 = rnd32(v2); v3 = rnd32(v3);
            }
            if (aSrc) {
                float a0 = aSrc[c0], a1 = aSrc[c0 + 1];
                float d0 = aDst[c0], d1 = aDst[c0 + 1];
                saR[mt][0] += v0 * a0 + v1 * a1;
                sdR[mt][0] += v0 * d0 + v1 * d1;
                saR[mt][1] += v2 * a0 + v3 * a1;
                sdR[mt][1] += v2 * d0 + v3 * d1;
            }
            if (r0 < M) {
                C[(size_t)r0 * N + c0] = v0;
                C[(size_t)r0 * N + c0 + 1] = v1;
            }
            if (r0 + 8 < M) {
                C[(size_t)(r0 + 8) * N + c0] = v2;
                C[(size_t)(r0 + 8) * N + c0 + 1] = v3;
            }
        }
    }

    if (aSrc) {
        int hd = warpN >> 6;
        #pragma unroll
        for (int mt = 0; mt < 2; mt++)
            #pragma unroll
            for (int hf = 0; hf < 2; hf++) {
                float vs = saR[mt][hf];
                float vd = sdR[mt][hf];
                vs += __shfl_xor_sync(0xffffffffu, vs, 1);
                vs += __shfl_xor_sync(0xffffffffu, vs, 2);
                vd += __shfl_xor_sync(0xffffffffu, vd, 1);
                vd += __shfl_xor_sync(0xffffffffu, vd, 2);
                int row = rb + warpM + mt * 16 + (lane >> 2) + hf * 8;
                if ((lane & 3) == 0 && row < M) {
                    asOut[row * 2 + hd] = vs;
                    adOut[row * 2 + hd] = vd;
                }
            }
    }
}

// ================= specialized logits GEMM (N=16, K=256) =====================
// BM=256, BK=32; 256 threads as 4(tx) x 64(ty); each thread 4 rows x 4 cols.
__global__ __launch_bounds__(256) void k_logits(
    const float* __restrict__ A, const float* __restrict__ B,
    const float* __restrict__ bias, float* __restrict__ C, int M)
{
    __shared__ float As[256][33];
    __shared__ float Bs[32][17];
    const int tid = threadIdx.x;
    const int tx = tid & 3;
    const int ty = tid >> 2;
    const int rb = blockIdx.x * 256;
    float acc[4][4] = {};

    for (int k0 = 0; k0 < 256; k0 += 32) {
        #pragma unroll
        for (int i = 0; i < 8; i++) {
            int f = tid + i * 256;
            int r = f >> 3, c4 = (f & 7) * 4;
            int gr = rb + r; if (gr >= M) gr = M - 1;
            float4 v = *(const float4*)(A + (size_t)gr * 256 + k0 + c4);
            As[r][c4] = v.x; As[r][c4 + 1] = v.y;
            As[r][c4 + 2] = v.z; As[r][c4 + 3] = v.w;
        }
        if (tid < 128) {
            int r = tid >> 2, c4 = (tid & 3) * 4;
            float4 v = *(const float4*)(B + (size_t)(k0 + r) * 16 + c4);
            Bs[r][c4] = v.x; Bs[r][c4 + 1] = v.y;
            Bs[r][c4 + 2] = v.z; Bs[r][c4 + 3] = v.w;
        }
        __syncthreads();

        #pragma unroll
        for (int k = 0; k < 32; k++) {
            float a[4], b[4];
            #pragma unroll
            for (int i = 0; i < 4; i++) a[i] = As[ty * 4 + i][k];
            #pragma unroll
            for (int j = 0; j < 4; j++) b[j] = Bs[k][tx * 4 + j];
            #pragma unroll
            for (int i = 0; i < 4; i++)
                #pragma unroll
                for (int j = 0; j < 4; j++)
                    acc[i][j] = fmaf(a[i], b[j], acc[i][j]);
        }
        __syncthreads();
    }

    #pragma unroll
    for (int i = 0; i < 4; i++) {
        int r = rb + ty * 4 + i;
        if (r >= M) continue;
        #pragma unroll
        for (int j = 0; j < 4; j++)
            C[(size_t)r * 16 + tx * 4 + j] = acc[i][j] + bias[tx * 4 + j];
    }
}

// ================= CSR construction ==========================================
__global__ __launch_bounds__(256) void k_zero(int* p, int n) {
    int i = blockIdx.x * blockDim.x + threadIdx.x;
    if (i < n) p[i] = 0;
}
__global__ __launch_bounds__(256) void k_hist4(
    const int* __restrict__ ei, int* deg, int nE)
{
    int i = blockIdx.x * blockDim.x + threadIdx.x;
    int base = i * 4;
    if (base + 3 < nE) {
        int4 d = *(const int4*)(ei + nE + base);
        atomicAdd(&deg[d.x], 1);
        atomicAdd(&deg[d.y], 1);
        atomicAdd(&deg[d.z], 1);
        atomicAdd(&deg[d.w], 1);
    } else {
        for (int j = base; j < nE; j++) atomicAdd(&deg[ei[nE + j]], 1);
    }
}
__global__ __launch_bounds__(SCAN_BLK) void k_scan1(
    const int* __restrict__ deg, int* incl, int* bsums, int n)
{
    __shared__ int sh[SCAN_BLK];
    int i = blockIdx.x * SCAN_BLK + threadIdx.x;
    int v = (i < n) ? deg[i] : 0;
    sh[threadIdx.x] = v;
    __syncthreads();
    for (int off = 1; off < SCAN_BLK; off <<= 1) {
        int t = (threadIdx.x >= off) ? sh[threadIdx.x - off] : 0;
        __syncthreads();
        sh[threadIdx.x] += t;
        __syncthreads();
    }
    if (i < n) incl[i] = sh[threadIdx.x];
    if (threadIdx.x == SCAN_BLK - 1) bsums[blockIdx.x] = sh[SCAN_BLK - 1];
}
__global__ __launch_bounds__(1024) void k_scan2(int* bsums, int nb) {
    __shared__ int sh[1024];
    int i = threadIdx.x;
    sh[i] = (i < nb) ? bsums[i] : 0;
    __syncthreads();
    for (int off = 1; off < 1024; off <<= 1) {
        int t = (i >= off) ? sh[i - off] : 0;
        __syncthreads();
        sh[i] += t;
        __syncthreads();
    }
    if (i < nb) bsums[i] = sh[i];
}
__global__ __launch_bounds__(SCAN_BLK) void k_scan3(
    const int* __restrict__ incl, const int* __restrict__ bsums,
    const int* __restrict__ deg, int* rowptr, int* cursor, int n)
{
    int i = blockIdx.x * SCAN_BLK + threadIdx.x;
    if (i >= n) return;
    int off = (blockIdx.x > 0) ? bsums[blockIdx.x - 1] : 0;
    int inc = incl[i] + off;
    rowptr[i + 1] = inc;
    cursor[i] = inc - deg[i];
    if (i == 0) rowptr[0] = 0;
}
__global__ __launch_bounds__(256) void k_scatter4(
    const int* __restrict__ ei, int* cursor, int* csrc, int nE)
{
    int i = blockIdx.x * blockDim.x + threadIdx.x;
    int base = i * 4;
    if (base + 3 < nE) {
        int4 s = *(const int4*)(ei + base);
        int4 d = *(const int4*)(ei + nE + base);
        int p0 = atomicAdd(&cursor[d.x], 1);
        int p1 = atomicAdd(&cursor[d.y], 1);
        int p2 = atomicAdd(&cursor[d.z], 1);
        int p3 = atomicAdd(&cursor[d.w], 1);
        csrc[p0] = s.x; csrc[p1] = s.y; csrc[p2] = s.z; csrc[p3] = s.w;
    } else {
        for (int j = base; j < nE; j++) {
            int pos = atomicAdd(&cursor[ei[nE + j]], 1);
            csrc[pos] = ei[j];
        }
    }
}

// ---------------- gather aggregation: warp per dst node (fp32, 8-wide) -------
__global__ __launch_bounds__(256) void k_gather(
    const int* __restrict__ rowptr, const int* __restrict__ csrc,
    const float* __restrict__ h, const float* __restrict__ as_,
    const float* __restrict__ ad_, const float* __restrict__ bias,
    float* __restrict__ out, int n, int rndOut)
{
    int w = (blockIdx.x * blockDim.x + threadIdx.x) >> 5;
    int lane = threadIdx.x & 31;
    if (w >= n) return;
    int hd = lane >> 4;

    float add = ad_[w * 2 + hd];
    float wself = expf(leaky(as_[w * 2 + hd] + add));
    float4 hv = ((const float4*)(h + (size_t)w * 128))[lane];
    float4 acc = make_float4(hv.x * wself, hv.y * wself, hv.z * wself, hv.w * wself);
    float den = wself;

    int j = rowptr[w], end = rowptr[w + 1];
    for (; j + 7 < end; j += 8) {
        int s[8];
        #pragma unroll
        for (int q = 0; q < 8; q++) s[q] = csrc[j + q];
        float wq[8];
        #pragma unroll
        for (int q = 0; q < 8; q++) wq[q] = expf(leaky(as_[s[q] * 2 + hd] + add));
        float4 hq[8];
        #pragma unroll
        for (int q = 0; q < 8; q++)
            hq[q] = ((const float4*)(h + (size_t)s[q] * 128))[lane];
        #pragma unroll
        for (int q = 0; q < 8; q++) {
            acc.x += wq[q] * hq[q].x;
            acc.y += wq[q] * hq[q].y;
            acc.z += wq[q] * hq[q].z;
            acc.w += wq[q] * hq[q].w;
            den += wq[q];
        }
    }
    for (; j + 1 < end; j += 2) {
        int s0 = csrc[j], s1 = csrc[j + 1];
        float w0 = expf(leaky(as_[s0 * 2 + hd] + add));
        float w1 = expf(leaky(as_[s1 * 2 + hd] + add));
        float4 h0 = ((const float4*)(h + (size_t)s0 * 128))[lane];
        float4 h1 = ((const float4*)(h + (size_t)s1 * 128))[lane];
        acc.x += w0 * h0.x + w1 * h1.x;
        acc.y += w0 * h0.y + w1 * h1.y;
        acc.z += w0 * h0.z + w1 * h1.z;
        acc.w += w0 * h0.w + w1 * h1.w;
        den += w0 + w1;
    }
    if (j < end) {
        int s0 = csrc[j];
        float w0 = expf(leaky(as_[s0 * 2 + hd] + add));
        float4 h0 = ((const float4*)(h + (size_t)s0 * 128))[lane];
        acc.x += w0 * h0.x; acc.y += w0 * h0.y;
        acc.z += w0 * h0.z; acc.w += w0 * h0.w;
        den += w0;
    }

    float inv = 1.f / (den + 1e-16f);
    float4 b = ((const float4*)bias)[lane];
    float4 o;
    o.x = fmaxf(acc.x * inv + b.x, 0.f);
    o.y = fmaxf(acc.y * inv + b.y, 0.f);
    o.z = fmaxf(acc.z * inv + b.z, 0.f);
    o.w = fmaxf(acc.w * inv + b.w, 0.f);
    if (rndOut) {
        o.x = rnd32(o.x); o.y = rnd32(o.y);
        o.z = rnd32(o.z); o.w = rnd32(o.w);
    }
    ((float4*)(out + (size_t)w * 128))[lane] = o;
}

// ---------------- launch ------------------------------------------------------
extern "C" void kernel_launch(void* const* d_in, const int* in_sizes, int n_in,
                              void* d_out, int out_size)
{
    const float* x   = (const float*)d_in[0];
    const int*   ei  = (const int*)  d_in[1];
    const float* W1  = (const float*)d_in[2];
    const float* as1 = (const float*)d_in[3];
    const float* ad1 = (const float*)d_in[4];
    const float* b1  = (const float*)d_in[5];
    const float* W2  = (const float*)d_in[6];
    const float* as2 = (const float*)d_in[7];
    const float* ad2 = (const float*)d_in[8];
    const float* b2  = (const float*)d_in[9];
    const float* lw1 = (const float*)d_in[10];
    const float* lb1 = (const float*)d_in[11];
    const float* lw2 = (const float*)d_in[12];
    const float* lb2 = (const float*)d_in[13];
    const float* lw3 = (const float*)d_in[14];
    const float* lb3 = (const float*)d_in[15];
    float* out = (float*)d_out;

    int n = in_sizes[0] / 64;
    int e = in_sizes[1] / 2;

    float *h, *tmp, *embS, *as_, *ad_, *z1, *z2;
    float *w1r, *w2r, *lw1r, *lw2r;
    int *deg, *incl, *bsums, *rowptr, *cursor, *csrc;
    cudaGetSymbolAddress((void**)&h,    g_h);
    cudaGetSymbolAddress((void**)&tmp,  g_tmp);
    cudaGetSymbolAddress((void**)&embS, g_emb);
    cudaGetSymbolAddress((void**)&as_,  g_as);
    cudaGetSymbolAddress((void**)&ad_,  g_ad);
    cudaGetSymbolAddress((void**)&z1,   g_z1);
    cudaGetSymbolAddress((void**)&z2,   g_z2);
    cudaGetSymbolAddress((void**)&w1r,  g_w1r);
    cudaGetSymbolAddress((void**)&w2r,  g_w2r);
    cudaGetSymbolAddress((void**)&lw1r, g_lw1r);
    cudaGetSymbolAddress((void**)&lw2r, g_lw2r);
    cudaGetSymbolAddress((void**)&deg,    g_deg);
    cudaGetSymbolAddress((void**)&incl,   g_incl);
    cudaGetSymbolAddress((void**)&bsums,  g_bsums);
    cudaGetSymbolAddress((void**)&rowptr, g_rowptr);
    cudaGetSymbolAddress((void**)&cursor, g_cursor);
    cudaGetSymbolAddress((void**)&csrc,   g_csrc);

    float* embPtr;
    float* logitsPtr;
    if ((long)out_size >= (long)n * 144) {
        embPtr = out;
        logitsPtr = out + (size_t)n * 128;
    } else {
        embPtr = embS;
        logitsPtr = out;
    }

    // ---- pre-round weights to tf32 ----
    const int wtot = 64*128 + 128*128 + 128*512 + 512*256;
    k_round_w<<<(wtot + 255) / 256, 256>>>(W1, w1r, W2, w2r, lw1, lw1r, lw2, lw2r);

    // ---- build CSR by destination ----
    int nscan = (n + SCAN_BLK - 1) / SCAN_BLK;
    int e4 = (e + 3) / 4;
    k_zero<<<(n + 255) / 256, 256>>>(deg, n);
    k_hist4<<<(e4 + 255) / 256, 256>>>(ei, deg, e);
    k_scan1<<<nscan, SCAN_BLK>>>(deg, incl, bsums, n);
    k_scan2<<<1, 1024>>>(bsums, nscan);
    k_scan3<<<nscan, SCAN_BLK>>>(incl, bsums, deg, rowptr, cursor, n);
    k_scatter4<<<(e4 + 255) / 256, 256>>>(ei, cursor, csrc, e);

    unsigned gy128 = (n + 127) / 128;
    int nodeGrid = (n * 32 + 255) / 256;

    // ---- GAT layer 1 (alpha fused into GEMM epilogue) ----
    k_gemm_tc<<<dim3(1, gy128), 256>>>(x, w1r, nullptr, h, n, 128, 64, 0, 0, 1,
                                       as1, ad1, as_, ad_);
    k_gather<<<nodeGrid, 256>>>(rowptr, csrc, h, as_, ad_, b1, tmp, n, 1);

    // ---- GAT layer 2 ----
    k_gemm_tc<<<dim3(1, gy128), 256>>>(tmp, w2r, nullptr, h, n, 128, 128, 0, 0, 0,
                                       as2, ad2, as_, ad_);
    k_gather<<<nodeGrid, 256>>>(rowptr, csrc, h, as_, ad_, b2, embPtr, n, 0);

    // ---- MLP head ----
    k_gemm_tc<<<dim3(4, gy128), 256>>>(embPtr, lw1r, lb1, z1, n, 512, 128, 1, 1, 1,
                                       nullptr, nullptr, nullptr, nullptr);
    k_gemm_tc<<<dim3(2, gy128), 256>>>(z1, lw2r, lb2, z2, n, 256, 512, 1, 0, 0,
                                       nullptr, nullptr, nullptr, nullptr);
    k_logits<<<(n + 255) / 256, 256>>>(z2, lw3, lb3, logitsPtr, n);
}